// round 1
// baseline (speedup 1.0000x reference)
#include <cuda_runtime.h>

// out[r, c] = x[r, c] * diag[c], x: 16384 x 2048 f32, diag: 2048 f32.
// Pure HBM-streaming kernel: float4 vectorized, one float4 per thread.
// 2048 cols / 4 = 512 float4 columns (power of two) -> col index = i & 511.
// diag (8 KB) stays resident in L1/L2; x/out traffic is the roofline.

__global__ __launch_bounds__(256) void diag_scale_kernel(
    const float4* __restrict__ x,
    const float4* __restrict__ d,
    float4* __restrict__ out)
{
    unsigned int i = blockIdx.x * 256u + threadIdx.x;
    float4 v = x[i];
    float4 s = __ldg(&d[i & 511u]);
    v.x *= s.x;
    v.y *= s.y;
    v.z *= s.z;
    v.w *= s.w;
    out[i] = v;
}

extern "C" void kernel_launch(void* const* d_in, const int* in_sizes, int n_in,
                              void* d_out, int out_size) {
    const float4* x = (const float4*)d_in[0];   // 16384*2048 f32
    const float4* d = (const float4*)d_in[1];   // 2048 f32
    float4* out = (float4*)d_out;

    // 16384*2048 / 4 = 8,388,608 float4 elements
    const int n4 = (16384 * 2048) / 4;
    const int threads = 256;
    const int blocks = n4 / threads;  // 32768, exact

    diag_scale_kernel<<<blocks, threads>>>(x, d, out);
}